// round 1
// baseline (speedup 1.0000x reference)
#include <cuda_runtime.h>
#include <math.h>

// Problem constants
#define Bn   4
#define Sn   2048
#define En   768
#define DFFn 3072
#define MTOT (Bn * Sn)          // 8192
#define LNEPS 1e-5f

// ---------------------------------------------------------------------------
// Scratch (allocation-free: __device__ globals)
// ---------------------------------------------------------------------------
__device__ float g_q  [MTOT * En];
__device__ float g_k  [MTOT * En];
__device__ float g_v  [MTOT * En];
__device__ float g_s  [(size_t)Bn * Sn * Sn];   // attention scores / probs
__device__ float g_h  [MTOT * En];              // attention output
__device__ float g_x1 [MTOT * En];
__device__ float g_x2 [MTOT * En];
__device__ float g_hid[MTOT * DFFn];
__device__ float g_mlp[MTOT * En];

// ---------------------------------------------------------------------------
// GEMM NT: C[M,N] = A[M,K] * B[N,K]^T (+ epilogue)
// EPI = 0: + bias       EPI = 1: relu(+ bias)       EPI = 2: * scale
// Tiles: BM=128, BN=64, BK=16, 256 threads, 8x4 per thread.
// All dims are multiples of tile sizes for this problem -> no bounds checks.
// ---------------------------------------------------------------------------
template<int EPI>
__global__ void __launch_bounds__(256)
gemm_nt_k(const float* __restrict__ A, const float* __restrict__ B,
          const float* __restrict__ bias, float* __restrict__ C,
          int M, int N, int K,
          long sA, long sB, long sC, float scale, int causal)
{
    constexpr int BM = 128, BN = 64, BK = 16;
    __shared__ float As[BK][BM + 2];
    __shared__ float Bs[BK][BN + 2];

    A += (long)blockIdx.z * sA;
    B += (long)blockIdx.z * sB;
    C += (long)blockIdx.z * sC;

    const int rm = blockIdx.y * BM;
    const int cn = blockIdx.x * BN;
    if (causal && cn > rm + (BM - 1)) return;   // block fully above diagonal

    const int tid = threadIdx.x;
    const int tx = tid & 15;          // 0..15 -> N
    const int ty = tid >> 4;          // 0..15 -> M
    const int lr = tid >> 2;          // 0..63  loader row
    const int lc = (tid & 3) << 2;    // 0,4,8,12 loader col (float4)

    float acc[8][4];
#pragma unroll
    for (int i = 0; i < 8; i++)
#pragma unroll
        for (int j = 0; j < 4; j++) acc[i][j] = 0.f;

    const float* Ap0 = A + (long)(rm + lr) * K + lc;
    const float* Ap1 = Ap0 + 64L * K;
    const float* Bp  = B + (long)(cn + lr) * K + lc;

    for (int k0 = 0; k0 < K; k0 += BK) {
        float4 a0 = *(const float4*)(Ap0 + k0);
        float4 a1 = *(const float4*)(Ap1 + k0);
        float4 b0 = *(const float4*)(Bp  + k0);
        As[lc + 0][lr]      = a0.x; As[lc + 1][lr]      = a0.y;
        As[lc + 2][lr]      = a0.z; As[lc + 3][lr]      = a0.w;
        As[lc + 0][lr + 64] = a1.x; As[lc + 1][lr + 64] = a1.y;
        As[lc + 2][lr + 64] = a1.z; As[lc + 3][lr + 64] = a1.w;
        Bs[lc + 0][lr] = b0.x; Bs[lc + 1][lr] = b0.y;
        Bs[lc + 2][lr] = b0.z; Bs[lc + 3][lr] = b0.w;
        __syncthreads();
#pragma unroll
        for (int kk = 0; kk < BK; kk++) {
            float a[8], b[4];
#pragma unroll
            for (int i = 0; i < 8; i++) a[i] = As[kk][ty * 8 + i];
#pragma unroll
            for (int j = 0; j < 4; j++) b[j] = Bs[kk][tx * 4 + j];
#pragma unroll
            for (int i = 0; i < 8; i++)
#pragma unroll
                for (int j = 0; j < 4; j++) acc[i][j] += a[i] * b[j];
        }
        __syncthreads();
    }

#pragma unroll
    for (int i = 0; i < 8; i++) {
        const int r = rm + ty * 8 + i;
        float4 o;
        float* op = (float*)&o;
#pragma unroll
        for (int j = 0; j < 4; j++) {
            const int c = cn + tx * 4 + j;
            float vv = acc[i][j];
            if (EPI == 0)      vv = vv + bias[c];
            else if (EPI == 1) vv = fmaxf(vv + bias[c], 0.f);
            else               vv = vv * scale;
            op[j] = vv;
        }
        *(float4*)(C + (long)r * N + cn + tx * 4) = o;
    }
}

// ---------------------------------------------------------------------------
// GEMM NN: C[M,N] = A[M,K] * B[K,N]   (used for P @ V)
// ---------------------------------------------------------------------------
__global__ void __launch_bounds__(256)
gemm_nn_k(const float* __restrict__ A, const float* __restrict__ B,
          float* __restrict__ C, int M, int N, int K,
          long sA, long sB, long sC)
{
    constexpr int BM = 128, BN = 64, BK = 16;
    __shared__ float As[BK][BM + 2];
    __shared__ float Bs[BK][BN + 2];

    A += (long)blockIdx.z * sA;
    B += (long)blockIdx.z * sB;
    C += (long)blockIdx.z * sC;

    const int rm = blockIdx.y * BM;
    const int cn = blockIdx.x * BN;

    const int tid = threadIdx.x;
    const int tx = tid & 15;
    const int ty = tid >> 4;
    const int lr = tid >> 2;          // A loader: 0..63
    const int lc = (tid & 3) << 2;
    const int br = tid >> 4;          // B loader: k row 0..15
    const int bc = (tid & 15) << 2;   // B loader: n col (float4)

    float acc[8][4];
#pragma unroll
    for (int i = 0; i < 8; i++)
#pragma unroll
        for (int j = 0; j < 4; j++) acc[i][j] = 0.f;

    const float* Ap0 = A + (long)(rm + lr) * K + lc;
    const float* Ap1 = Ap0 + 64L * K;

    for (int k0 = 0; k0 < K; k0 += BK) {
        float4 a0 = *(const float4*)(Ap0 + k0);
        float4 a1 = *(const float4*)(Ap1 + k0);
        float4 b0 = *(const float4*)(B + (long)(k0 + br) * N + cn + bc);
        As[lc + 0][lr]      = a0.x; As[lc + 1][lr]      = a0.y;
        As[lc + 2][lr]      = a0.z; As[lc + 3][lr]      = a0.w;
        As[lc + 0][lr + 64] = a1.x; As[lc + 1][lr + 64] = a1.y;
        As[lc + 2][lr + 64] = a1.z; As[lc + 3][lr + 64] = a1.w;
        Bs[br][bc + 0] = b0.x; Bs[br][bc + 1] = b0.y;
        Bs[br][bc + 2] = b0.z; Bs[br][bc + 3] = b0.w;
        __syncthreads();
#pragma unroll
        for (int kk = 0; kk < BK; kk++) {
            float a[8], b[4];
#pragma unroll
            for (int i = 0; i < 8; i++) a[i] = As[kk][ty * 8 + i];
#pragma unroll
            for (int j = 0; j < 4; j++) b[j] = Bs[kk][tx * 4 + j];
#pragma unroll
            for (int i = 0; i < 8; i++)
#pragma unroll
                for (int j = 0; j < 4; j++) acc[i][j] += a[i] * b[j];
        }
        __syncthreads();
    }

#pragma unroll
    for (int i = 0; i < 8; i++) {
        const int r = rm + ty * 8 + i;
        float4 o;
        ((float*)&o)[0] = acc[i][0];
        ((float*)&o)[1] = acc[i][1];
        ((float*)&o)[2] = acc[i][2];
        ((float*)&o)[3] = acc[i][3];
        *(float4*)(C + (long)r * N + cn + tx * 4) = o;
    }
}

// ---------------------------------------------------------------------------
// Row softmax over scores; causal rows use length L=i+1, masked tail -> 0.
// One block (256 threads) per row.
// ---------------------------------------------------------------------------
__global__ void __launch_bounds__(256)
softmax_k(float* __restrict__ P, int causal)
{
    const int row = blockIdx.x;
    const int b = row >> 11;        // / 2048
    const int i = row & 2047;
    float* p = P + (long)b * Sn * Sn + (long)i * Sn;
    const int L = causal ? (i + 1) : Sn;
    const int tid = threadIdx.x;
    __shared__ float sh[8];

    float m = -3.4e38f;
    for (int j = tid; j < L; j += 256) m = fmaxf(m, p[j]);
#pragma unroll
    for (int o = 16; o > 0; o >>= 1) m = fmaxf(m, __shfl_xor_sync(~0u, m, o));
    if ((tid & 31) == 0) sh[tid >> 5] = m;
    __syncthreads();
    m = sh[0];
#pragma unroll
    for (int w = 1; w < 8; w++) m = fmaxf(m, sh[w]);

    float s = 0.f;
    for (int j = tid; j < L; j += 256) {
        float e = __expf(p[j] - m);
        p[j] = e;
        s += e;
    }
#pragma unroll
    for (int o = 16; o > 0; o >>= 1) s += __shfl_xor_sync(~0u, s, o);
    __syncthreads();
    if ((tid & 31) == 0) sh[tid >> 5] = s;
    __syncthreads();
    s = 0.f;
#pragma unroll
    for (int w = 0; w < 8; w++) s += sh[w];
    const float inv = 1.f / s;

    for (int j = tid; j < L; j += 256) p[j] *= inv;
    for (int j = L + tid; j < Sn; j += 256) p[j] = 0.f;   // masked tail -> 0
}

// ---------------------------------------------------------------------------
// y = LayerNorm(x + h) * g + b   (row length En = 768, 256 thr x 3 elems)
// ---------------------------------------------------------------------------
__global__ void __launch_bounds__(256)
add_ln_k(const float* __restrict__ x, const float* __restrict__ h,
         const float* __restrict__ g, const float* __restrict__ bt,
         float* __restrict__ y)
{
    const long row = blockIdx.x;
    const float* xr = x + row * En;
    const float* hr = h + row * En;
    float* yr = y + row * En;
    const int tid = threadIdx.x;

    float v[3];
    float s = 0.f, s2 = 0.f;
#pragma unroll
    for (int t = 0; t < 3; t++) {
        const int c = tid + t * 256;
        const float u = xr[c] + hr[c];
        v[t] = u;
        s += u;
        s2 += u * u;
    }
    __shared__ float shA[8], shB[8];
#pragma unroll
    for (int o = 16; o > 0; o >>= 1) {
        s  += __shfl_xor_sync(~0u, s,  o);
        s2 += __shfl_xor_sync(~0u, s2, o);
    }
    if ((tid & 31) == 0) { shA[tid >> 5] = s; shB[tid >> 5] = s2; }
    __syncthreads();
    s = 0.f; s2 = 0.f;
#pragma unroll
    for (int w = 0; w < 8; w++) { s += shA[w]; s2 += shB[w]; }

    const float mu   = s * (1.f / En);
    const float var  = s2 * (1.f / En) - mu * mu;
    const float rstd = rsqrtf(var + LNEPS);
#pragma unroll
    for (int t = 0; t < 3; t++) {
        const int c = tid + t * 256;
        yr[c] = (v[t] - mu) * rstd * g[c] + bt[c];
    }
}

// ---------------------------------------------------------------------------
// Host launcher
// ---------------------------------------------------------------------------
extern "C" void kernel_launch(void* const* d_in, const int* in_sizes, int n_in,
                              void* d_out, int out_size)
{
    const float* x     = (const float*)d_in[0];
    const float* kv    = (const float*)d_in[1];
    const float* wq_w  = (const float*)d_in[2];
    const float* wq_b  = (const float*)d_in[3];
    const float* wk_w  = (const float*)d_in[4];
    const float* wk_b  = (const float*)d_in[5];
    const float* wv_w  = (const float*)d_in[6];
    const float* wv_b  = (const float*)d_in[7];
    const float* ln1_g = (const float*)d_in[8];
    const float* ln1_b = (const float*)d_in[9];
    const float* wq2_w = (const float*)d_in[10];
    const float* wq2_b = (const float*)d_in[11];
    const float* wk2_w = (const float*)d_in[12];
    const float* wk2_b = (const float*)d_in[13];
    const float* wv2_w = (const float*)d_in[14];
    const float* wv2_b = (const float*)d_in[15];
    const float* ln2_g = (const float*)d_in[16];
    const float* ln2_b = (const float*)d_in[17];
    const float* w1    = (const float*)d_in[18];
    const float* b1    = (const float*)d_in[19];
    const float* w2    = (const float*)d_in[20];
    const float* b2    = (const float*)d_in[21];
    const float* ln3_g = (const float*)d_in[22];
    const float* ln3_b = (const float*)d_in[23];
    float* out = (float*)d_out;

    float *pq, *pk, *pv, *ps, *ph, *px1, *px2, *phid, *pmlp;
    cudaGetSymbolAddress((void**)&pq,   g_q);
    cudaGetSymbolAddress((void**)&pk,   g_k);
    cudaGetSymbolAddress((void**)&pv,   g_v);
    cudaGetSymbolAddress((void**)&ps,   g_s);
    cudaGetSymbolAddress((void**)&ph,   g_h);
    cudaGetSymbolAddress((void**)&px1,  g_x1);
    cudaGetSymbolAddress((void**)&px2,  g_x2);
    cudaGetSymbolAddress((void**)&phid, g_hid);
    cudaGetSymbolAddress((void**)&pmlp, g_mlp);

    const float scale = 0.03608439182435161f;  // 1/sqrt(768)
    const long sQE = (long)Sn * En;             // per-batch q/k/v stride
    const long sSS = (long)Sn * Sn;             // per-batch score stride

    const dim3 gProj(En / 64, MTOT / 128, 1);       // 12 x 64
    const dim3 gScore(Sn / 64, Sn / 128, Bn);       // 32 x 16 x 4
    const dim3 gPV(En / 64, Sn / 128, Bn);          // 12 x 16 x 4
    const dim3 gFF1(DFFn / 64, MTOT / 128, 1);      // 48 x 64
    const dim3 gFF2(En / 64, MTOT / 128, 1);        // 12 x 64

    // ---- causal self-attention ----
    gemm_nt_k<0><<<gProj, 256>>>(x, wq_w, wq_b, pq, MTOT, En, En, 0, 0, 0, 1.f, 0);
    gemm_nt_k<0><<<gProj, 256>>>(x, wk_w, wk_b, pk, MTOT, En, En, 0, 0, 0, 1.f, 0);
    gemm_nt_k<0><<<gProj, 256>>>(x, wv_w, wv_b, pv, MTOT, En, En, 0, 0, 0, 1.f, 0);
    gemm_nt_k<2><<<gScore, 256>>>(pq, pk, nullptr, ps, Sn, Sn, En, sQE, sQE, sSS, scale, 1);
    softmax_k<<<MTOT, 256>>>(ps, 1);
    gemm_nn_k<<<gPV, 256>>>(ps, pv, ph, Sn, En, Sn, sSS, sQE, sQE);
    add_ln_k<<<MTOT, 256>>>(x, ph, ln1_g, ln1_b, px1);

    // ---- cross-attention (no mask) ----
    gemm_nt_k<0><<<gProj, 256>>>(px1, wq2_w, wq2_b, pq, MTOT, En, En, 0, 0, 0, 1.f, 0);
    gemm_nt_k<0><<<gProj, 256>>>(kv,  wk2_w, wk2_b, pk, MTOT, En, En, 0, 0, 0, 1.f, 0);
    gemm_nt_k<0><<<gProj, 256>>>(kv,  wv2_w, wv2_b, pv, MTOT, En, En, 0, 0, 0, 1.f, 0);
    gemm_nt_k<2><<<gScore, 256>>>(pq, pk, nullptr, ps, Sn, Sn, En, sQE, sQE, sSS, scale, 0);
    softmax_k<<<MTOT, 256>>>(ps, 0);
    gemm_nn_k<<<gPV, 256>>>(ps, pv, ph, Sn, En, Sn, sSS, sQE, sQE);
    add_ln_k<<<MTOT, 256>>>(px1, ph, ln2_g, ln2_b, px2);

    // ---- MLP: relu(x@w1^T+b1) -> relu(h@w2^T+b2) -> LN(x + mlp) ----
    gemm_nt_k<1><<<gFF1, 256>>>(px2, w1, b1, phid, MTOT, DFFn, En, 0, 0, 0, 1.f, 0);
    gemm_nt_k<1><<<gFF2, 256>>>(phid, w2, b2, pmlp, MTOT, En, DFFn, 0, 0, 0, 1.f, 0);
    add_ln_k<<<MTOT, 256>>>(px2, pmlp, ln3_g, ln3_b, out);
}

// round 3
// speedup vs baseline: 2.4744x; 2.4744x over previous
#include <cuda_runtime.h>
#include <cstdint>
#include <math.h>

// ---------------------------------------------------------------------------
// Problem constants
// ---------------------------------------------------------------------------
#define Bn   4
#define Sn   2048
#define En   768
#define DFFn 3072
#define MTOT (Bn * Sn)          // 8192
#define LNEPS 1e-5f

// Arch-specific feature gate: tcgen05/TMEM exist only on sm_100a/sm_103a (and
// family targets). The harness also builds a plain compute_103 PTX pass which
// rejects those instructions, so every tcgen05 use must sit behind this gate.
#if defined(__CUDA_ARCH__) && \
    (defined(__CUDA_ARCH_FEAT_SM103_ALL) || defined(__CUDA_ARCH_FEAT_SM100_ALL) || \
     defined(__CUDA_ARCH_FEAT_SM101_ALL) || \
     (defined(__CUDA_ARCH_SPECIFIC__)        && (__CUDA_ARCH_SPECIFIC__        >= 1000)) || \
     (defined(__CUDA_ARCH_FAMILY_SPECIFIC__) && (__CUDA_ARCH_FAMILY_SPECIFIC__ >= 1000)))
#define HAS_TC 1
#else
#define HAS_TC 0
#endif

// ---------------------------------------------------------------------------
// Scratch (allocation-free: __device__ globals)
// ---------------------------------------------------------------------------
__device__ float g_q  [MTOT * En];
__device__ float g_k  [MTOT * En];
__device__ float g_vt [MTOT * En];              // V transposed: [En, MTOT]
__device__ float g_s  [(size_t)Bn * Sn * Sn];   // attention scores / probs
__device__ float g_h  [MTOT * En];              // attention output
__device__ float g_x1 [MTOT * En];
__device__ float g_x2 [MTOT * En];
__device__ float g_hid[(size_t)MTOT * DFFn];
__device__ float g_mlp[MTOT * En];

// ---------------------------------------------------------------------------
// PTX helpers (compiled only on "a"/family targets)
// ---------------------------------------------------------------------------
__device__ __forceinline__ uint32_t smem_u32(const void* p) {
    uint32_t a;
    asm("{ .reg .u64 t; cvta.to.shared.u64 t, %1; cvt.u32.u64 %0, t; }"
        : "=r"(a) : "l"(p));
    return a;
}

#if HAS_TC
__device__ __forceinline__ uint32_t elect_one() {
    uint32_t pred;
    asm volatile("{\n\t.reg .pred p;\n\telect.sync _|p, 0xFFFFFFFF;\n\t"
                 "selp.b32 %0, 1, 0, p;\n\t}" : "=r"(pred));
    return pred;
}

#define MBARRIER_INIT(addr, cnt) \
    asm volatile("mbarrier.init.shared.b64 [%0], %1;" :: "r"(addr), "r"(cnt) : "memory")

#define MBARRIER_WAIT_PARITY(mbar_addr, phase_parity) do {                          \
    uint32_t _mbar = (uint32_t)(mbar_addr);                                         \
    uint32_t _par  = (uint32_t)(phase_parity);                                      \
    uint32_t _done;                                                                 \
    asm volatile("{\n\t.reg .pred p;\n\t"                                           \
        "mbarrier.try_wait.parity.acquire.cta.shared::cta.b64 p, [%1], %2;\n\t"     \
        "selp.b32 %0, 1, 0, p;\n\t}"                                                \
        : "=r"(_done) : "r"(_mbar), "r"(_par) : "memory");                          \
    if (!_done) {                                                                   \
        asm volatile("{\n\t.reg .pred P1;\n\t"                                      \
        "WAIT_LOOP_%=:\n\t"                                                         \
        "mbarrier.try_wait.parity.acquire.cta.shared::cta.b64 P1, [%0], %1, 0x989680;\n\t" \
        "@P1 bra.uni WAIT_DONE_%=;\n\t"                                             \
        "bra.uni WAIT_LOOP_%=;\n\t"                                                 \
        "WAIT_DONE_%=:\n\t}"                                                        \
        :: "r"(_mbar), "r"(_par) : "memory");                                       \
    }                                                                               \
} while (0)

#define TCGEN05_ALLOC(smem_res, ncols) \
    asm volatile("tcgen05.alloc.cta_group::1.sync.aligned.shared::cta.b32 [%0], %1;" \
                 :: "r"((uint32_t)(smem_res)), "r"((uint32_t)(ncols)) : "memory")
#define TCGEN05_DEALLOC(tmem, ncols) \
    asm volatile("tcgen05.dealloc.cta_group::1.sync.aligned.b32 %0, %1;" \
                 :: "r"(tmem), "r"((uint32_t)(ncols)))
#define TCGEN05_RELINQUISH() \
    asm volatile("tcgen05.relinquish_alloc_permit.cta_group::1.sync.aligned;")
#define TCGEN05_COMMIT(mbar) \
    asm volatile("tcgen05.commit.cta_group::1.mbarrier::arrive::one.shared::cluster.b64 [%0];" \
                 :: "r"((uint32_t)(mbar)) : "memory")
#define TCGEN05_FENCE_AFTER() \
    asm volatile("tcgen05.fence::after_thread_sync;" ::: "memory")
#define TCGEN05_FENCE_BEFORE() \
    asm volatile("tcgen05.fence::before_thread_sync;" ::: "memory")
#define TCGEN05_WAIT_LD() \
    asm volatile("tcgen05.wait::ld.sync.aligned;" ::: "memory")
#define FENCE_ASYNC_SHARED() \
    asm volatile("fence.proxy.async;" ::: "memory")

#define TCGEN05_LD_32X32B_X32(r, tmem_addr) \
    asm volatile( \
        "tcgen05.ld.sync.aligned.32x32b.x32.b32 " \
        "{%0, %1, %2, %3, %4, %5, %6, %7, " \
        " %8, %9, %10, %11, %12, %13, %14, %15, " \
        " %16, %17, %18, %19, %20, %21, %22, %23, " \
        " %24, %25, %26, %27, %28, %29, %30, %31}, [%32];" \
        : "=r"((r)[0]),  "=r"((r)[1]),  "=r"((r)[2]),  "=r"((r)[3]), \
          "=r"((r)[4]),  "=r"((r)[5]),  "=r"((r)[6]),  "=r"((r)[7]), \
          "=r"((r)[8]),  "=r"((r)[9]),  "=r"((r)[10]), "=r"((r)[11]), \
          "=r"((r)[12]), "=r"((r)[13]), "=r"((r)[14]), "=r"((r)[15]), \
          "=r"((r)[16]), "=r"((r)[17]), "=r"((r)[18]), "=r"((r)[19]), \
          "=r"((r)[20]), "=r"((r)[21]), "=r"((r)[22]), "=r"((r)[23]), \
          "=r"((r)[24]), "=r"((r)[25]), "=r"((r)[26]), "=r"((r)[27]), \
          "=r"((r)[28]), "=r"((r)[29]), "=r"((r)[30]), "=r"((r)[31]) \
        : "r"(tmem_addr))

// 64-bit SMEM matrix descriptor: SW128, Blackwell, LBO=1, SBO=64 (K-major,
// 128-byte rows) — the layout validated by the example kernels.
__device__ __forceinline__ uint64_t make_desc(uint32_t addr) {
    constexpr uint64_t base =
        (uint64_t(2)  << 61) | (uint64_t(1) << 46) |
        (uint64_t(64) << 32) | (uint64_t(1) << 16);
    return base | ((uint64_t)(addr >> 4) & 0x3FFF);
}

// tcgen05.mma kind::tf32, SS form, cta_group::1.
// idesc: D=f32 (1<<4), A=TF32 (2<<7), B=TF32 (2<<10), N/8<<17, M/16<<24.
__device__ __forceinline__ void mma_tf32(uint32_t d_tmem, uint64_t da, uint64_t db,
                                         uint32_t idesc, uint32_t acc) {
    asm volatile(
        "{\n\t.reg .pred p;\n\tsetp.ne.u32 p, %4, 0;\n\t"
        "tcgen05.mma.cta_group::1.kind::tf32 [%0], %1, %2, %3, {%5, %5, %5, %5}, p;\n\t}"
        :: "r"(d_tmem), "l"(da), "l"(db), "r"(idesc), "r"(acc), "r"(0u)
        : "memory");
}
#endif  // HAS_TC

__device__ __forceinline__ float tf32_round(float x) {
    uint32_t u;
    asm("cvt.rna.tf32.f32 %0, %1;" : "=r"(u) : "f"(x));
    return __uint_as_float(u);
}

// ---------------------------------------------------------------------------
// GEMM (NT): C[M,N] = A[M,K] * B[N,K]^T (+ epilogue)
//   EPI 0: +bias   1: relu(+bias)   2: *scale   3: +bias, transposed store   4: plain
// tcgen05 path: BM=BN=128, BK=32, 3xTF32 split, 2-stage smem double buffer.
// Fallback path (non-"a" target): SIMT fp32, 128x128 tile, 8x8/thread.
// All dims are multiples of tile sizes for this problem -> no bounds checks.
// ---------------------------------------------------------------------------
static constexpr int SM_TILE0   = 1024;
static constexpr int SM_STAGE   = 65536;       // 4 tiles x 16KB
static constexpr int SM_A_HI    = 0;
static constexpr int SM_A_LO    = 16384;
static constexpr int SM_B_HI    = 32768;
static constexpr int SM_B_LO    = 49152;
static constexpr int GEMM_SMEM  = SM_TILE0 + 2 * SM_STAGE;   // 132096 B
static constexpr uint32_t IDESC_128 =
    (1u << 4) | (2u << 7) | (2u << 10) | ((128u / 8u) << 17) | ((128u / 16u) << 24);

#if HAS_TC
__device__ __forceinline__ void load_split(const float* __restrict__ g, int ld,
                                           long koff, char* hi, char* lo, int tid)
{
#pragma unroll
    for (int i = 0; i < 4; i++) {
        const int q   = i * 256 + tid;          // 0..1023 quads (128 rows x 8)
        const int row = q >> 3;
        const int qc  = q & 7;
        const float4 f = *(const float4*)(g + (long)row * ld + koff + qc * 4);
        float4 h, l;
        h.x = tf32_round(f.x); l.x = f.x - h.x;
        h.y = tf32_round(f.y); l.y = f.y - h.y;
        h.z = tf32_round(f.z); l.z = f.z - h.z;
        h.w = tf32_round(f.w); l.w = f.w - h.w;
        uint32_t off = (uint32_t)(row * 128 + qc * 16);
        off ^= (off >> 3) & 0x70;               // SW128 swizzle (16B granular)
        *(float4*)(hi + off) = h;
        *(float4*)(lo + off) = l;
    }
}
#endif

template<int EPI>
__global__ void __launch_bounds__(288, 1)
gemm_tc(const float* __restrict__ A, const float* __restrict__ B,
        const float* __restrict__ bias, float* __restrict__ C,
        int K, int lda, int ldb, int ldc,
        long sA, long sB, long sC, float scale, int causal)
{
    extern __shared__ __align__(1024) char smem[];
    const int tid = threadIdx.x;

    const int rm = blockIdx.y * 128;
    const int cn = blockIdx.x * 128;
    if (causal && cn > rm + 127) return;        // block fully above diagonal

    A += (long)blockIdx.z * sA;
    B += (long)blockIdx.z * sB;
    C += (long)blockIdx.z * sC;

#if HAS_TC
    // ------------------------- tcgen05 3xTF32 path -------------------------
    const uint32_t smem_base = smem_u32(smem);
    const int wid = tid >> 5;

    if (tid == 0) {
        MBARRIER_INIT(smem_base + 8, 1);
        MBARRIER_INIT(smem_base + 16, 1);
    }
    if (wid == 8) TCGEN05_ALLOC(smem_base + 0, 128);
    __syncthreads();

    uint32_t tmem;
    asm volatile("ld.shared.b32 %0, [%1];" : "=r"(tmem) : "r"(smem_base));

    const int NC = K >> 5;
    const float* Ab = A + (long)rm * lda;
    const float* Bb = B + (long)cn * ldb;

    if (tid < 256) {                            // preload chunk 0 -> stage 0
        char* t0 = smem + SM_TILE0;
        load_split(Ab, lda, 0, t0 + SM_A_HI, t0 + SM_A_LO, tid);
        load_split(Bb, ldb, 0, t0 + SM_B_HI, t0 + SM_B_LO, tid);
        FENCE_ASYNC_SHARED();
    }
    __syncthreads();

    for (int c = 0; c < NC; c++) {
        const int s = c & 1;
        if (wid == 8 && elect_one()) {
            const uint32_t tb = smem_base + SM_TILE0 + s * SM_STAGE;
            const uint64_t dah = make_desc(tb + SM_A_HI);
            const uint64_t dal = make_desc(tb + SM_A_LO);
            const uint64_t dbh = make_desc(tb + SM_B_HI);
            const uint64_t dbl = make_desc(tb + SM_B_LO);
#pragma unroll
            for (int st = 0; st < 4; st++)       // hi*hi
                mma_tf32(tmem, dah + st * 2, dbh + st * 2, IDESC_128,
                         (c == 0 && st == 0) ? 0u : 1u);
#pragma unroll
            for (int st = 0; st < 4; st++)       // hi*lo
                mma_tf32(tmem, dah + st * 2, dbl + st * 2, IDESC_128, 1u);
#pragma unroll
            for (int st = 0; st < 4; st++)       // lo*hi
                mma_tf32(tmem, dal + st * 2, dbh + st * 2, IDESC_128, 1u);
            TCGEN05_COMMIT(smem_base + 8 + s * 8);
        }
        if (tid < 256 && c + 1 < NC) {
            if (c >= 1)   // stage s^1 still holds chunk c-1's operands
                MBARRIER_WAIT_PARITY(smem_base + 8 + (s ^ 1) * 8, ((c - 1) >> 1) & 1);
            char* tn = smem + SM_TILE0 + (s ^ 1) * SM_STAGE;
            const long koff = (long)(c + 1) << 5;
            load_split(Ab, lda, koff, tn + SM_A_HI, tn + SM_A_LO, tid);
            load_split(Bb, ldb, koff, tn + SM_B_HI, tn + SM_B_LO, tid);
            FENCE_ASYNC_SHARED();
        }
        __syncthreads();
    }

    MBARRIER_WAIT_PARITY(smem_base + 8 + ((NC - 1) & 1) * 8, ((NC - 1) >> 1) & 1);
    TCGEN05_FENCE_AFTER();

    if (wid < 4) {
        const int lane = tid & 31;
        const int m = rm + wid * 32 + lane;      // TMEM lane -> D row
#pragma unroll
        for (int seg = 0; seg < 4; seg++) {
            uint32_t r[32];
            TCGEN05_LD_32X32B_X32(r, tmem + seg * 32);
            TCGEN05_WAIT_LD();
            if (EPI == 3) {
#pragma unroll
                for (int j = 0; j < 32; j++) {
                    const int n = cn + seg * 32 + j;
                    C[(long)n * ldc + m] = __uint_as_float(r[j]) + bias[n];
                }
            } else {
#pragma unroll
                for (int j = 0; j < 32; j += 4) {
                    float v[4];
#pragma unroll
                    for (int t = 0; t < 4; t++) {
                        const int n = cn + seg * 32 + j + t;
                        float x = __uint_as_float(r[j + t]);
                        if (EPI == 0)      x += bias[n];
                        else if (EPI == 1) x = fmaxf(x + bias[n], 0.f);
                        else if (EPI == 2) x *= scale;
                        v[t] = x;
                    }
                    *(float4*)(C + (long)m * ldc + cn + seg * 32 + j) =
                        make_float4(v[0], v[1], v[2], v[3]);
                }
            }
        }
        TCGEN05_FENCE_BEFORE();
    }
    __syncthreads();
    if (wid == 8) {
        TCGEN05_RELINQUISH();
        TCGEN05_DEALLOC(tmem, 128);
    }
#else
    // --------------------- SIMT fp32 fallback path -------------------------
    // 256 compute threads; warp 8 only participates in __syncthreads.
    constexpr int BK = 16;
    float (*As)[132] = (float (*)[132])(smem);
    float (*Bs)[132] = (float (*)[132])(smem + BK * 132 * sizeof(float));

    const int tx = tid & 15, ty = tid >> 4;      // 16x16 threads (tid<256)
    float acc[8][8];
#pragma unroll
    for (int i = 0; i < 8; i++)
#pragma unroll
        for (int j = 0; j < 8; j++) acc[i][j] = 0.f;

    const float* Ab = A + (long)rm * lda;
    const float* Bb = B + (long)cn * ldb;

    for (int k0 = 0; k0 < K; k0 += BK) {
        if (tid < 256) {
#pragma unroll
            for (int i = 0; i < 2; i++) {
                const int q = i * 256 + tid;     // 512 float4 per tile
                const int row = q >> 2, qc = q & 3;
                float4 fa = *(const float4*)(Ab + (long)row * lda + k0 + qc * 4);
                float4 fb = *(const float4*)(Bb + (long)row * ldb + k0 + qc * 4);
                As[qc * 4 + 0][row] = fa.x; As[qc * 4 + 1][row] = fa.y;
                As[qc * 4 + 2][row] = fa.z; As[qc * 4 + 3][row] = fa.w;
                Bs[qc * 4 + 0][row] = fb.x; Bs[qc * 4 + 1][row] = fb.y;
                Bs[qc * 4 + 2][row] = fb.z; Bs[qc * 4 + 3][row] = fb.w;
            }
        }
        __syncthreads();
        if (tid < 256) {
#pragma unroll
            for (int kk = 0; kk < BK; kk++) {
                float a[8], b[8];
#pragma unroll
                for (int i = 0; i < 8; i++) a[i] = As[kk][ty * 8 + i];
#pragma unroll
                for (int j = 0; j < 8; j++) b[j] = Bs[kk][tx * 8 + j];
#pragma unroll
                for (int i = 0; i < 8; i++)
#pragma unroll
                    for (int j = 0; j < 8; j++) acc[i][j] += a[i] * b[j];
            }
        }
        __syncthreads();
    }

    if (tid < 256) {
#pragma unroll
        for (int i = 0; i < 8; i++) {
            const int m = rm + ty * 8 + i;
            if (EPI == 3) {
#pragma unroll
                for (int j = 0; j < 8; j++) {
                    const int n = cn + tx * 8 + j;
                    C[(long)n * ldc + m] = acc[i][j] + bias[n];
                }
            } else {
#pragma unroll
                for (int j = 0; j < 8; j += 4) {
                    float v[4];
#pragma unroll
                    for (int t = 0; t < 4; t++) {
                        const int n = cn + tx * 8 + j + t;
                        float x = acc[i][j + t];
                        if (EPI == 0)      x += bias[n];
                        else if (EPI == 1) x = fmaxf(x + bias[n], 0.f);
                        else if (EPI == 2) x *= scale;
                        v[t] = x;
                    }
                    *(float4*)(C + (long)m * ldc + cn + tx * 8 + j) =
                        make_float4(v[0], v[1], v[2], v[3]);
                }
            }
        }
    }
#endif
}

// ---------------------------------------------------------------------------
// Row softmax; causal rows use length L=i+1, masked tail -> 0.
// ---------------------------------------------------------------------------
__global__ void __launch_bounds__(256)
softmax_k(float* __restrict__ P, int causal)
{
    const int row = blockIdx.x;
    const int b = row >> 11;
    const int i = row & 2047;
    float* p = P + (long)b * Sn * Sn + (long)i * Sn;
    const int L = causal ? (i + 1) : Sn;
    const int tid = threadIdx.x;
    __shared__ float sh[8];

    float m = -3.4e38f;
    for (int j = tid; j < L; j += 256) m = fmaxf(m, p[j]);
#pragma unroll
    for (int o = 16; o > 0; o >>= 1) m = fmaxf(m, __shfl_xor_sync(~0u, m, o));
    if ((tid & 31) == 0) sh[tid >> 5] = m;
    __syncthreads();
    m = sh[0];
#pragma unroll
    for (int w = 1; w < 8; w++) m = fmaxf(m, sh[w]);

    float s = 0.f;
    for (int j = tid; j < L; j += 256) {
        float e = __expf(p[j] - m);
        p[j] = e;
        s += e;
    }
#pragma unroll
    for (int o = 16; o > 0; o >>= 1) s += __shfl_xor_sync(~0u, s, o);
    __syncthreads();
    if ((tid & 31) == 0) sh[tid >> 5] = s;
    __syncthreads();
    s = 0.f;
#pragma unroll
    for (int w = 0; w < 8; w++) s += sh[w];
    const float inv = 1.f / s;

    for (int j = tid; j < L; j += 256) p[j] *= inv;
    for (int j = L + tid; j < Sn; j += 256) p[j] = 0.f;
}

// ---------------------------------------------------------------------------
// y = LayerNorm(x + h) * g + b   (row length En = 768)
// ---------------------------------------------------------------------------
__global__ void __launch_bounds__(256)
add_ln_k(const float* __restrict__ x, const float* __restrict__ h,
         const float* __restrict__ g, const float* __restrict__ bt,
         float* __restrict__ y)
{
    const long row = blockIdx.x;
    const float* xr = x + row * En;
    const float* hr = h + row * En;
    float* yr = y + row * En;
    const int tid = threadIdx.x;

    float v[3];
    float s = 0.f, s2 = 0.f;
#pragma unroll
    for (int t = 0; t < 3; t++) {
        const int c = tid + t * 256;
        const float u = xr[c] + hr[c];
        v[t] = u;
        s += u;
        s2 += u * u;
    }
    __shared__ float shA[8], shB[8];
#pragma unroll
    for (int o = 16; o > 0; o >>= 1) {
        s  += __shfl_xor_sync(~0u, s,  o);
        s2 += __shfl_xor_sync(~0u, s2, o);
    }
    if ((tid & 31) == 0) { shA[tid >> 5] = s; shB[tid >> 5] = s2; }
    __syncthreads();
    s = 0.f; s2 = 0.f;
#pragma unroll
    for (int w = 0; w < 8; w++) { s += shA[w]; s2 += shB[w]; }

    const float mu   = s * (1.f / En);
    const float var  = s2 * (1.f / En) - mu * mu;
    const float rstd = rsqrtf(var + LNEPS);
#pragma unroll
    for (int t = 0; t < 3; t++) {
        const int c = tid + t * 256;
        yr[c] = (v[t] - mu) * rstd * g[c] + bt[c];
    }
}

// ---------------------------------------------------------------------------
// Host launcher
// ---------------------------------------------------------------------------
extern "C" void kernel_launch(void* const* d_in, const int* in_sizes, int n_in,
                              void* d_out, int out_size)
{
    const float* x     = (const float*)d_in[0];
    const float* kv    = (const float*)d_in[1];
    const float* wq_w  = (const float*)d_in[2];
    const float* wq_b  = (const float*)d_in[3];
    const float* wk_w  = (const float*)d_in[4];
    const float* wk_b  = (const float*)d_in[5];
    const float* wv_w  = (const float*)d_in[6];
    const float* wv_b  = (const float*)d_in[7];
    const float* ln1_g = (const float*)d_in[8];
    const float* ln1_b = (const float*)d_in[9];
    const float* wq2_w = (const float*)d_in[10];
    const float* wq2_b = (const float*)d_in[11];
    const float* wk2_w = (const float*)d_in[12];
    const float* wk2_b = (const float*)d_in[13];
    const float* wv2_w = (const float*)d_in[14];
    const float* wv2_b = (const float*)d_in[15];
    const float* ln2_g = (const float*)d_in[16];
    const float* ln2_b = (const float*)d_in[17];
    const float* w1    = (const float*)d_in[18];
    const float* b1    = (const float*)d_in[19];
    const float* w2    = (const float*)d_in[20];
    const float* b2    = (const float*)d_in[21];
    const float* ln3_g = (const float*)d_in[22];
    const float* ln3_b = (const float*)d_in[23];
    float* out = (float*)d_out;

    float *pq, *pk, *pvt, *ps, *ph, *px1, *px2, *phid, *pmlp;
    cudaGetSymbolAddress((void**)&pq,   g_q);
    cudaGetSymbolAddress((void**)&pk,   g_k);
    cudaGetSymbolAddress((void**)&pvt,  g_vt);
    cudaGetSymbolAddress((void**)&ps,   g_s);
    cudaGetSymbolAddress((void**)&ph,   g_h);
    cudaGetSymbolAddress((void**)&px1,  g_x1);
    cudaGetSymbolAddress((void**)&px2,  g_x2);
    cudaGetSymbolAddress((void**)&phid, g_hid);
    cudaGetSymbolAddress((void**)&pmlp, g_mlp);

    cudaFuncSetAttribute(gemm_tc<0>, cudaFuncAttributeMaxDynamicSharedMemorySize, GEMM_SMEM);
    cudaFuncSetAttribute(gemm_tc<1>, cudaFuncAttributeMaxDynamicSharedMemorySize, GEMM_SMEM);
    cudaFuncSetAttribute(gemm_tc<2>, cudaFuncAttributeMaxDynamicSharedMemorySize, GEMM_SMEM);
    cudaFuncSetAttribute(gemm_tc<3>, cudaFuncAttributeMaxDynamicSharedMemorySize, GEMM_SMEM);
    cudaFuncSetAttribute(gemm_tc<4>, cudaFuncAttributeMaxDynamicSharedMemorySize, GEMM_SMEM);

    const float scale = 0.03608439182435161f;  // 1/sqrt(768)
    const long sQE = (long)Sn * En;
    const long sSS = (long)Sn * Sn;

    const dim3 gProj(En / 128, MTOT / 128, 1);       // 6 x 64
    const dim3 gScore(Sn / 128, Sn / 128, Bn);       // 16 x 16 x 4
    const dim3 gPV(En / 128, Sn / 128, Bn);          // 6 x 16 x 4
    const dim3 gFF1(DFFn / 128, MTOT / 128, 1);      // 24 x 64
    const dim3 gFF2(En / 128, MTOT / 128, 1);        // 6 x 64

    // ---- causal self-attention ----
    gemm_tc<0><<<gProj, 288, GEMM_SMEM>>>(x, wq_w, wq_b, pq, En, En, En, En, 0, 0, 0, 1.f, 0);
    gemm_tc<0><<<gProj, 288, GEMM_SMEM>>>(x, wk_w, wk_b, pk, En, En, En, En, 0, 0, 0, 1.f, 0);
    gemm_tc<3><<<gProj, 288, GEMM_SMEM>>>(x, wv_w, wv_b, pvt, En, En, En, MTOT, 0, 0, 0, 1.f, 0);
    gemm_tc<2><<<gScore, 288, GEMM_SMEM>>>(pq, pk, nullptr, ps, En, En, En, Sn,
                                           sQE, sQE, sSS, scale, 1);
    softmax_k<<<MTOT, 256>>>(ps, 1);
    gemm_tc<4><<<gPV, 288, GEMM_SMEM>>>(ps, pvt, nullptr, ph, Sn, Sn, MTOT, En,
                                        sSS, (long)Sn, sQE, 1.f, 0);
    add_ln_k<<<MTOT, 256>>>(x, ph, ln1_g, ln1_b, px1);

    // ---- cross-attention (no mask) ----
    gemm_tc<0><<<gProj, 288, GEMM_SMEM>>>(px1, wq2_w, wq2_b, pq, En, En, En, En, 0, 0, 0, 1.f, 0);
    gemm_tc<0><<<gProj, 288, GEMM_SMEM>>>(kv,  wk2_w, wk2_b, pk, En, En, En, En, 0, 0, 0, 1.f, 0);
    gemm_tc<3><<<gProj, 288, GEMM_SMEM>>>(kv,  wv2_w, wv2_b, pvt, En, En, En, MTOT, 0, 0, 0, 1.f, 0);
    gemm_tc<2><<<gScore, 288, GEMM_SMEM>>>(pq, pk, nullptr, ps, En, En, En, Sn,
                                           sQE, sQE, sSS, scale, 0);
    softmax_k<<<MTOT, 256>>>(ps, 0);
    gemm_tc<4><<<gPV, 288, GEMM_SMEM>>>(ps, pvt, nullptr, ph, Sn, Sn, MTOT, En,
                                        sSS, (long)Sn, sQE, 1.f, 0);
    add_ln_k<<<MTOT, 256>>>(px1, ph, ln2_g, ln2_b, px2);

    // ---- MLP ----
    gemm_tc<1><<<gFF1, 288, GEMM_SMEM>>>(px2, w1, b1, phid, En, En, En, DFFn, 0, 0, 0, 1.f, 0);
    gemm_tc<1><<<gFF2, 288, GEMM_SMEM>>>(phid, w2, b2, pmlp, DFFn, DFFn, DFFn, En, 0, 0, 0, 1.f, 0);
    add_ln_k<<<MTOT, 256>>>(px2, pmlp, ln3_g, ln3_b, out);
}